// round 4
// baseline (speedup 1.0000x reference)
#include <cuda_runtime.h>
#include <stdint.h>

// ---------------------------------------------------------------------------
// TwoWL: 2-layer 2-WL coloring on N=256 node graph.
// Output: 3 histograms (atomic + 2 layers), each length M=65536, written to
// d_out as FLOAT32 (counts are < 2^24 so exact).
//
//   - Atomic coloring key: (x[v1]<<5 | x[v2]<<1 | A) < 512 -> direct table,
//     relabeled by first occurrence in "permutations then diagonal" order.
//   - Layer coloring key: (label<<16 | rowclass<<8 | colclass) where
//     rowclass/colclass are equality classes of sorted row/col multisets.
//     Relabel via lock-free hash (CAS insert + atomicMin pos).
//   - Rank assignment: scatter first-occurrence marks, exclusive scan, gather.
// ---------------------------------------------------------------------------

#define NN 256
#define MM 65536
#define TAB 131072
#define TABMASK (TAB - 1)
#define ATAB 1024
#define ATABMASK (ATAB - 1)

__device__ int                g_A[MM];        // adjacency indicator (0/1)
__device__ int                g_labels[MM];
__device__ int                g_rowsorted[MM];
__device__ int                g_colsorted[MM];
__device__ int                g_rowclass[NN];
__device__ int                g_colclass[NN];
__device__ unsigned long long g_tab[TAB];
__device__ unsigned int       g_minpos[TAB];
__device__ unsigned int       g_aminpos[ATAB];
__device__ int                g_slotid[MM];
__device__ int                g_mark[MM];
__device__ int                g_rank[MM];
__device__ int                g_hist[MM];     // int staging for one histogram

__device__ __forceinline__ unsigned int hash32(unsigned int x) {
    x ^= x >> 16; x *= 0x7feb352du;
    x ^= x >> 15; x *= 0x846ca68bu;
    x ^= x >> 16;
    return x;
}

// ---------------------------------------------------------------------------
// Init: zero output + adjacency + atomic table + staging + marks
// ---------------------------------------------------------------------------
__global__ void k_init(float* out, int out_size) {
    int gid = blockIdx.x * blockDim.x + threadIdx.x;
    int stride = gridDim.x * blockDim.x;
    for (int i = gid; i < out_size; i += stride) out[i] = 0.0f;
    for (int i = gid; i < MM; i += stride) {
        g_A[i] = 0;
        g_hist[i] = 0;
        g_mark[i] = 0;
    }
    if (gid < ATAB) g_aminpos[gid] = 0xFFFFFFFFu;
}

__global__ void k_edges(const int* __restrict__ ei, int E) {
    int e = blockIdx.x * blockDim.x + threadIdx.x;
    if (e < E) {
        unsigned int s = (unsigned int)ei[e] & 255u;
        unsigned int d = (unsigned int)ei[E + e] & 255u;
        g_A[s * NN + d] = 1;
    }
}

// ---------------------------------------------------------------------------
// Atomic layer: direct table keyed by (x1<<5 | x2<<1 | A)
// ---------------------------------------------------------------------------
__device__ __forceinline__ unsigned int atomic_key(const int* __restrict__ x, int idx) {
    int i = idx >> 8;
    int j = idx & 255;
    unsigned int key = ((unsigned int)x[i] << 5) | ((unsigned int)x[j] << 1)
                     | (unsigned int)g_A[idx];
    return key & ATABMASK;
}

__device__ __forceinline__ unsigned int atomic_pos(int idx) {
    int i = idx >> 8;
    int j = idx & 255;
    if (i == j) return (unsigned int)(NN * (NN - 1) + i);
    return (unsigned int)(i * (NN - 1) + (j < i ? j : j - 1));
}

__global__ void k_insert_atomic(const int* __restrict__ x) {
    int idx = blockIdx.x * blockDim.x + threadIdx.x;
    if (idx < MM) atomicMin(&g_aminpos[atomic_key(x, idx)], atomic_pos(idx));
}

__global__ void k_mark_atomic() {
    int t = blockIdx.x * blockDim.x + threadIdx.x;
    if (t < ATAB) {
        unsigned int p = g_aminpos[t];
        if (p < (unsigned int)MM) g_mark[p] = 1;
    }
}

__global__ void k_assign_atomic(const int* __restrict__ x) {
    int idx = blockIdx.x * blockDim.x + threadIdx.x;
    if (idx >= MM) return;
    unsigned int p = g_aminpos[atomic_key(x, idx)] & (MM - 1);
    int lbl = g_rank[p] & (MM - 1);
    g_labels[idx] = lbl;
    atomicAdd(&g_hist[lbl], 1);
}

// Emit staged int histogram as float32, and clear staging + marks for reuse.
__global__ void k_emit(float* __restrict__ dst, int avail) {
    int idx = blockIdx.x * blockDim.x + threadIdx.x;
    if (idx >= MM) return;
    if (idx < avail) dst[idx] = (float)g_hist[idx];
    g_hist[idx] = 0;
    g_mark[idx] = 0;
}

// ---------------------------------------------------------------------------
// Layer relabel machinery (hash table)
// ---------------------------------------------------------------------------
__global__ void k_clear_tab() {
    int gid = blockIdx.x * blockDim.x + threadIdx.x;
    int stride = gridDim.x * blockDim.x;
    for (int i = gid; i < TAB; i += stride) {
        g_tab[i] = 0ULL;
        g_minpos[i] = 0xFFFFFFFFu;
    }
}

__global__ void k_insert_layer() {
    int idx = blockIdx.x * blockDim.x + threadIdx.x;
    if (idx >= MM) return;
    int i = idx >> 8;
    int j = idx & 255;
    unsigned int key = ((unsigned int)g_labels[idx] << 16)
                     | (((unsigned int)g_rowclass[i] & 255u) << 8)
                     | ((unsigned int)g_colclass[j] & 255u);
    unsigned long long stored = (((unsigned long long)key) << 1) | 1ULL;
    unsigned int h = hash32(key) & TABMASK;
    for (;;) {
        unsigned long long old = atomicCAS(&g_tab[h], 0ULL, stored);
        if (old == 0ULL || old == stored) break;
        h = (h + 1) & TABMASK;
    }
    atomicMin(&g_minpos[h], (unsigned int)idx);
    g_slotid[idx] = (int)h;
}

__global__ void k_mark() {
    int gid = blockIdx.x * blockDim.x + threadIdx.x;
    int stride = gridDim.x * blockDim.x;
    for (int t = gid; t < TAB; t += stride) {
        if (g_tab[t] != 0ULL) {
            unsigned int p = g_minpos[t];
            if (p < (unsigned int)MM) g_mark[p] = 1;
        }
    }
}

// Single-block exclusive scan of g_mark[0..MM) -> g_rank.
__global__ void k_scan() {
    __shared__ int sh[1024];
    __shared__ int carry_sh;
    int t = threadIdx.x;
    if (t == 0) carry_sh = 0;
    __syncthreads();
    for (int base = 0; base < MM; base += 1024) {
        int v = g_mark[base + t];
        sh[t] = v;
        __syncthreads();
        for (int off = 1; off < 1024; off <<= 1) {
            int tmp = (t >= off) ? sh[t - off] : 0;
            __syncthreads();
            sh[t] += tmp;
            __syncthreads();
        }
        int carry = carry_sh;
        g_rank[base + t] = carry + sh[t] - v;
        __syncthreads();
        if (t == 0) carry_sh += sh[1023];
        __syncthreads();
    }
}

__global__ void k_assign() {
    int idx = blockIdx.x * blockDim.x + threadIdx.x;
    if (idx >= MM) return;
    unsigned int slot = (unsigned int)g_slotid[idx] & TABMASK;
    unsigned int p = g_minpos[slot] & (MM - 1);
    int lbl = g_rank[p] & (MM - 1);
    g_labels[idx] = lbl;
    atomicAdd(&g_hist[lbl], 1);
}

// ---------------------------------------------------------------------------
// Row / col sorting (bitonic, 256 elems per block) + equality classification
// ---------------------------------------------------------------------------
__device__ __forceinline__ void bitonic256(int* s, int t) {
    for (int k = 2; k <= 256; k <<= 1) {
        for (int j = k >> 1; j > 0; j >>= 1) {
            int ixj = t ^ j;
            if (ixj > t) {
                bool up = ((t & k) == 0);
                int a = s[t], b = s[ixj];
                if ((a > b) == up) { s[t] = b; s[ixj] = a; }
            }
            __syncthreads();
        }
    }
}

__global__ void k_sort_rows() {
    __shared__ int s[256];
    int r = blockIdx.x, t = threadIdx.x;
    s[t] = g_labels[(r << 8) + t];
    __syncthreads();
    bitonic256(s, t);
    g_rowsorted[(r << 8) + t] = s[t];
}

__global__ void k_sort_cols() {
    __shared__ int s[256];
    int c = blockIdx.x, t = threadIdx.x;
    s[t] = g_labels[(t << 8) + c];
    __syncthreads();
    bitonic256(s, t);
    g_colsorted[(c << 8) + t] = s[t];
}

// cls[i] = min j such that sorted-vector j equals sorted-vector i.
__global__ void k_classify(int which) {
    const int* sorted = which ? g_colsorted : g_rowsorted;
    int* cls = which ? g_colclass : g_rowclass;
    int i = blockIdx.x, t = threadIdx.x;
    __shared__ int ref[256];
    __shared__ int res;
    ref[t] = sorted[(i << 8) + t];
    if (t == 0) res = i;
    __syncthreads();
    if (t < i) {
        const int* rj = sorted + (t << 8);
        bool eq = true;
        #pragma unroll 8
        for (int k = 0; k < 256; k++) {
            if (rj[k] != ref[k]) { eq = false; break; }
        }
        if (eq) atomicMin(&res, t);
    }
    __syncthreads();
    if (t == 0) cls[i] = res;
}

// ---------------------------------------------------------------------------
// Host launch
// ---------------------------------------------------------------------------
extern "C" void kernel_launch(void* const* d_in, const int* in_sizes, int n_in,
                              void* d_out, int out_size) {
    // Select inputs BY SIZE (x is the smaller buffer in any units).
    int xi = 0, ei_i = 1;
    if (n_in >= 2 && in_sizes[0] > in_sizes[1]) { xi = 1; ei_i = 0; }
    const int* x  = (const int*)d_in[xi];
    const int* ei = (const int*)d_in[ei_i];
    int E = in_sizes[ei_i] / 2;
    if (E == 4 * 8192) E = 8192;   // in_sizes given in bytes -> correct it
    float* out = (float*)d_out;

    k_init<<<256, 256>>>(out, out_size);
    k_edges<<<(E + 255) / 256, 256>>>(ei, E);

    // --- atomic coloring (direct table) ---
    k_insert_atomic<<<256, 256>>>(x);
    k_mark_atomic<<<4, 256>>>();
    k_scan<<<1, 1024>>>();
    k_assign_atomic<<<256, 256>>>(x);
    {
        int avail = out_size;
        if (avail > MM) avail = MM;
        k_emit<<<256, 256>>>(out, avail);
    }

    // --- 2 refinement layers ---
    for (int l = 0; l < 2; l++) {
        k_sort_rows<<<256, 256>>>();
        k_sort_cols<<<256, 256>>>();
        k_classify<<<256, 256>>>(0);
        k_classify<<<256, 256>>>(1);
        k_clear_tab<<<256, 256>>>();
        k_insert_layer<<<256, 256>>>();
        k_mark<<<256, 256>>>();
        k_scan<<<1, 1024>>>();
        k_assign<<<256, 256>>>();
        int off = (l + 1) * MM;
        int avail = out_size - off;
        if (avail > MM) avail = MM;
        if (avail > 0) k_emit<<<256, 256>>>(out + off, avail);
    }
}

// round 5
// speedup vs baseline: 3.0059x; 3.0059x over previous
#include <cuda_runtime.h>
#include <stdint.h>

// ---------------------------------------------------------------------------
// TwoWL: 2-layer 2-WL coloring, N=256, M=65536. Output: 3 float32 histograms.
// ---------------------------------------------------------------------------

#define NN 256
#define MM 65536
#define TAB 131072
#define TABMASK (TAB - 1)
#define ATAB 1024
#define ATABMASK (ATAB - 1)

__device__ int                g_A[MM];
__device__ int                g_labels[MM];
__device__ int4               g_rowsorted4[MM / 4];
__device__ int4               g_colsorted4[MM / 4];
__device__ int                g_rowclass[NN];
__device__ int                g_colclass[NN];
__device__ unsigned long long g_tab[TAB];
__device__ unsigned int       g_minpos[TAB];
__device__ unsigned int       g_aminpos[ATAB];
__device__ int                g_slotid[MM];
__device__ int4               g_mark4[MM / 4];
__device__ int4               g_rank4[MM / 4];
__device__ int                g_bsum[64];
__device__ int                g_boff[64];
__device__ int                g_hist[MM];

#define g_mark      ((int*)g_mark4)
#define g_rank      ((int*)g_rank4)
#define g_rowsorted ((int*)g_rowsorted4)
#define g_colsorted ((int*)g_colsorted4)

__device__ __forceinline__ unsigned int hash32(unsigned int x) {
    x ^= x >> 16; x *= 0x7feb352du;
    x ^= x >> 15; x *= 0x846ca68bu;
    x ^= x >> 16;
    return x;
}

// ---------------------------------------------------------------------------
__global__ void k_init(float* out, int out_size) {
    int gid = blockIdx.x * blockDim.x + threadIdx.x;
    int stride = gridDim.x * blockDim.x;
    for (int i = gid; i < out_size; i += stride) out[i] = 0.0f;
    for (int i = gid; i < MM; i += stride) {
        g_A[i] = 0;
        g_hist[i] = 0;
        g_mark[i] = 0;
    }
    if (gid < ATAB) g_aminpos[gid] = 0xFFFFFFFFu;
}

__global__ void k_edges(const int* __restrict__ ei, int E) {
    int e = blockIdx.x * blockDim.x + threadIdx.x;
    if (e < E) {
        unsigned int s = (unsigned int)ei[e] & 255u;
        unsigned int d = (unsigned int)ei[E + e] & 255u;
        g_A[s * NN + d] = 1;
    }
}

// ---------------------------------------------------------------------------
// Atomic layer: direct table keyed by (x1<<5 | x2<<1 | A)
// ---------------------------------------------------------------------------
__device__ __forceinline__ unsigned int atomic_key(const int* __restrict__ x, int idx) {
    int i = idx >> 8;
    int j = idx & 255;
    unsigned int key = ((unsigned int)x[i] << 5) | ((unsigned int)x[j] << 1)
                     | (unsigned int)g_A[idx];
    return key & ATABMASK;
}

__device__ __forceinline__ unsigned int atomic_pos(int idx) {
    int i = idx >> 8;
    int j = idx & 255;
    if (i == j) return (unsigned int)(NN * (NN - 1) + i);
    return (unsigned int)(i * (NN - 1) + (j < i ? j : j - 1));
}

__global__ void k_insert_atomic(const int* __restrict__ x) {
    int idx = blockIdx.x * blockDim.x + threadIdx.x;
    if (idx < MM) atomicMin(&g_aminpos[atomic_key(x, idx)], atomic_pos(idx));
}

// Sort all 1024 table minpos values (empties = UINT_MAX sort last), scatter
// rank = sorted index into g_rank[pos]. One block, 512 threads.
__global__ void k_rank_atomic() {
    __shared__ unsigned int s[ATAB];
    int t = threadIdx.x;
    s[t]       = g_aminpos[t];
    s[t + 512] = g_aminpos[t + 512];
    __syncthreads();
    for (unsigned int k = 2; k <= ATAB; k <<= 1) {
        for (unsigned int j = k >> 1; j > 0; j >>= 1) {
            unsigned int idx = ((unsigned int)t & (j - 1)) | (((unsigned int)t & ~(j - 1)) << 1);
            unsigned int partner = idx | j;
            bool up = (idx & k) == 0;
            unsigned int a = s[idx], b = s[partner];
            if ((a > b) == up) { s[idx] = b; s[partner] = a; }
            __syncthreads();
        }
    }
    unsigned int v = s[t];
    if (v < (unsigned int)MM) g_rank[v] = t;
    v = s[t + 512];
    if (v < (unsigned int)MM) g_rank[v] = t + 512;
}

__global__ void k_assign_atomic(const int* __restrict__ x) {
    int idx = blockIdx.x * blockDim.x + threadIdx.x;
    if (idx >= MM) return;
    unsigned int p = g_aminpos[atomic_key(x, idx)] & (MM - 1);
    int lbl = g_rank[p] & (MM - 1);
    g_labels[idx] = lbl;
    atomicAdd(&g_hist[lbl], 1);
}

// Emit staged histogram as float32; clear staging, marks, and hash table.
__global__ void k_emit(float* __restrict__ dst, int avail) {
    int idx = blockIdx.x * blockDim.x + threadIdx.x;
    if (idx >= MM) return;
    if (idx < avail) dst[idx] = (float)g_hist[idx];
    g_hist[idx] = 0;
    g_mark[idx] = 0;
    g_tab[idx] = 0ULL;
    g_tab[idx + MM] = 0ULL;
    g_minpos[idx] = 0xFFFFFFFFu;
    g_minpos[idx + MM] = 0xFFFFFFFFu;
}

// ---------------------------------------------------------------------------
// Layer relabel (hash table)
// ---------------------------------------------------------------------------
__global__ void k_insert_layer() {
    int idx = blockIdx.x * blockDim.x + threadIdx.x;
    if (idx >= MM) return;
    int i = idx >> 8;
    int j = idx & 255;
    unsigned int key = ((unsigned int)g_labels[idx] << 16)
                     | (((unsigned int)g_rowclass[i] & 255u) << 8)
                     | ((unsigned int)g_colclass[j] & 255u);
    unsigned long long stored = (((unsigned long long)key) << 1) | 1ULL;
    unsigned int h = hash32(key) & TABMASK;
    for (;;) {
        unsigned long long old = atomicCAS(&g_tab[h], 0ULL, stored);
        if (old == 0ULL || old == stored) break;
        h = (h + 1) & TABMASK;
    }
    atomicMin(&g_minpos[h], (unsigned int)idx);
    g_slotid[idx] = (int)h;
}

__global__ void k_mark() {
    int t = blockIdx.x * blockDim.x + threadIdx.x;
    if (t < TAB && g_tab[t] != 0ULL) {
        unsigned int p = g_minpos[t];
        if (p < (unsigned int)MM) g_mark[p] = 1;
    }
}

// Phase 1: per-block (1024 elems) exclusive scan -> g_rank local, totals -> g_bsum
__global__ void k_scan1() {
    __shared__ int warp_sums[8];
    __shared__ int warp_excl[8];
    int b = blockIdx.x, t = threadIdx.x;
    int lane = t & 31, w = t >> 5;
    int4 v = g_mark4[b * 256 + t];
    int s01 = v.x + v.y;
    int s012 = s01 + v.z;
    int tot = s012 + v.w;
    int inc = tot;
    #pragma unroll
    for (int off = 1; off < 32; off <<= 1) {
        int n = __shfl_up_sync(0xFFFFFFFFu, inc, off);
        if (lane >= off) inc += n;
    }
    if (lane == 31) warp_sums[w] = inc;
    __syncthreads();
    if (t < 8) {
        int ws = warp_sums[t];
        int inc2 = ws;
        #pragma unroll
        for (int off = 1; off < 8; off <<= 1) {
            int n = __shfl_up_sync(0xFFu, inc2, off);
            if (t >= off) inc2 += n;
        }
        warp_excl[t] = inc2 - ws;
    }
    __syncthreads();
    int base = warp_excl[w] + inc - tot;
    int4 e;
    e.x = base;
    e.y = base + v.x;
    e.z = base + s01;
    e.w = base + s012;
    g_rank4[b * 256 + t] = e;
    if (t == 255) g_bsum[b] = warp_excl[7] + inc;
}

// Phase 2: exclusive scan of the 64 block sums
__global__ void k_scan2() {
    __shared__ int sh[64];
    int t = threadIdx.x;
    int v = g_bsum[t];
    sh[t] = v;
    __syncthreads();
    #pragma unroll
    for (int off = 1; off < 64; off <<= 1) {
        int tmp = (t >= off) ? sh[t - off] : 0;
        __syncthreads();
        sh[t] += tmp;
        __syncthreads();
    }
    g_boff[t] = sh[t] - v;
}

__global__ void k_assign() {
    int idx = blockIdx.x * blockDim.x + threadIdx.x;
    if (idx >= MM) return;
    unsigned int slot = (unsigned int)g_slotid[idx] & TABMASK;
    unsigned int p = g_minpos[slot] & (MM - 1);
    int lbl = (g_rank[p] + g_boff[p >> 10]) & (MM - 1);
    g_labels[idx] = lbl;
    atomicAdd(&g_hist[lbl], 1);
}

// ---------------------------------------------------------------------------
// Sort rows+cols (512 blocks) and classify (512 blocks)
// ---------------------------------------------------------------------------
__device__ __forceinline__ void bitonic256(int* s, int t) {
    for (int k = 2; k <= 256; k <<= 1) {
        for (int j = k >> 1; j > 0; j >>= 1) {
            int ixj = t ^ j;
            if (ixj > t) {
                bool up = ((t & k) == 0);
                int a = s[t], b = s[ixj];
                if ((a > b) == up) { s[t] = b; s[ixj] = a; }
            }
            __syncthreads();
        }
    }
}

__global__ void k_sort() {
    __shared__ int s[256];
    int b = blockIdx.x, t = threadIdx.x;
    bool isCol = b >= NN;
    int rc = b & (NN - 1);
    s[t] = isCol ? g_labels[(t << 8) + rc] : g_labels[(rc << 8) + t];
    __syncthreads();
    bitonic256(s, t);
    if (isCol) g_colsorted[(rc << 8) + t] = s[t];
    else       g_rowsorted[(rc << 8) + t] = s[t];
}

__global__ void k_classify() {
    int b = blockIdx.x, t = threadIdx.x;
    bool isCol = b >= NN;
    int i = b & (NN - 1);
    const int4* sorted = isCol ? g_colsorted4 : g_rowsorted4;
    __shared__ int4 ref[64];
    __shared__ int res;
    if (t < 64) ref[t] = sorted[(i << 6) + t];
    if (t == 0) res = i;
    __syncthreads();
    if (t < i) {
        const int4* rj = sorted + (t << 6);
        bool eq = true;
        for (int k = 0; k < 64; k++) {
            int4 a = rj[k];
            int4 r = ref[k];
            if (a.x != r.x || a.y != r.y || a.z != r.z || a.w != r.w) { eq = false; break; }
        }
        if (eq) atomicMin(&res, t);
    }
    __syncthreads();
    if (t == 0) {
        if (isCol) g_colclass[i] = res;
        else       g_rowclass[i] = res;
    }
}

// ---------------------------------------------------------------------------
extern "C" void kernel_launch(void* const* d_in, const int* in_sizes, int n_in,
                              void* d_out, int out_size) {
    int xi = 0, ei_i = 1;
    if (n_in >= 2 && in_sizes[0] > in_sizes[1]) { xi = 1; ei_i = 0; }
    const int* x  = (const int*)d_in[xi];
    const int* ei = (const int*)d_in[ei_i];
    int E = in_sizes[ei_i] / 2;
    if (E == 4 * 8192) E = 8192;
    float* out = (float*)d_out;

    k_init<<<256, 256>>>(out, out_size);
    k_edges<<<(E + 255) / 256, 256>>>(ei, E);

    // --- atomic coloring ---
    k_insert_atomic<<<256, 256>>>(x);
    k_rank_atomic<<<1, 512>>>();
    k_assign_atomic<<<256, 256>>>(x);
    {
        int avail = out_size < MM ? out_size : MM;
        k_emit<<<256, 256>>>(out, avail);
    }

    // --- 2 refinement layers ---
    for (int l = 0; l < 2; l++) {
        k_sort<<<512, 256>>>();
        k_classify<<<512, 256>>>();
        k_insert_layer<<<256, 256>>>();
        k_mark<<<512, 256>>>();
        k_scan1<<<64, 256>>>();
        k_scan2<<<1, 64>>>();
        k_assign<<<256, 256>>>();
        int off = (l + 1) * MM;
        int avail = out_size - off;
        if (avail > MM) avail = MM;
        if (avail > 0) k_emit<<<256, 256>>>(out + off, avail);
    }
}

// round 6
// speedup vs baseline: 4.3831x; 1.4581x over previous
#include <cuda_runtime.h>
#include <stdint.h>

// ---------------------------------------------------------------------------
// TwoWL: 2-layer 2-WL coloring, N=256, M=65536. Output: 3 float32 histograms.
//
// Multiset-hash formulation: row/col sorted-multiset equality replaced by a
// commutative 64-bit hash sum (deterministic; collision prob ~2^-32).
// ---------------------------------------------------------------------------

#define NN 256
#define MM 65536
#define TAB 131072
#define TABMASK (TAB - 1)
#define ATAB 1024
#define ATABMASK (ATAB - 1)

__device__ int                g_A[MM];
__device__ int                g_labels[MM];
__device__ unsigned long long g_rowsig[NN];
__device__ unsigned long long g_colsig[NN];
__device__ unsigned long long g_tab[TAB];
__device__ unsigned int       g_minpos[TAB];
__device__ int                g_count[TAB];
__device__ int                g_slotrank[TAB];
__device__ int                g_slotid[MM];
__device__ unsigned int       g_aminpos[ATAB];
__device__ int                g_acount[ATAB];
__device__ int                g_arank[ATAB];
__device__ int4               g_mark4[MM / 4];
__device__ int4               g_rank4[MM / 4];
__device__ int                g_bsum[64];
__device__ int                g_boff[64];
__device__ unsigned int       g_scancnt;

#define g_mark ((int*)g_mark4)
#define g_rank ((int*)g_rank4)

__device__ __forceinline__ unsigned long long sm64(unsigned long long z) {
    z += 0x9E3779B97F4A7C15ULL;
    z = (z ^ (z >> 30)) * 0xBF58476D1CE4E5B9ULL;
    z = (z ^ (z >> 27)) * 0x94D049BB133111EBULL;
    return z ^ (z >> 31);
}

__device__ __forceinline__ unsigned int hash32(unsigned int x) {
    x ^= x >> 16; x *= 0x7feb352du;
    x ^= x >> 15; x *= 0x846ca68bu;
    x ^= x >> 16;
    return x;
}

// ---------------------------------------------------------------------------
__global__ void k_init(float* out, int out_size) {
    int gid = blockIdx.x * blockDim.x + threadIdx.x;
    int stride = gridDim.x * blockDim.x;
    for (int i = gid; i < out_size; i += stride) out[i] = 0.0f;
    for (int i = gid; i < MM; i += stride) {
        g_A[i] = 0;
        g_mark[i] = 0;
    }
    for (int i = gid; i < TAB; i += stride) {
        g_tab[i] = 0ULL;
        g_minpos[i] = 0xFFFFFFFFu;
        g_count[i] = 0;
    }
    if (gid < ATAB) { g_aminpos[gid] = 0xFFFFFFFFu; g_acount[gid] = 0; }
    if (gid == 0) g_scancnt = 0u;
}

__global__ void k_edges(const int* __restrict__ ei, int E) {
    int e = blockIdx.x * blockDim.x + threadIdx.x;
    if (e < E) {
        unsigned int s = (unsigned int)ei[e] & 255u;
        unsigned int d = (unsigned int)ei[E + e] & 255u;
        g_A[s * NN + d] = 1;
    }
}

// ---------------------------------------------------------------------------
// Atomic layer
// ---------------------------------------------------------------------------
__device__ __forceinline__ unsigned int atomic_key(const int* __restrict__ x, int idx) {
    int i = idx >> 8;
    int j = idx & 255;
    unsigned int key = ((unsigned int)x[i] << 5) | ((unsigned int)x[j] << 1)
                     | (unsigned int)g_A[idx];
    return key & ATABMASK;
}

__global__ void k_insA(const int* __restrict__ x) {
    int idx = blockIdx.x * blockDim.x + threadIdx.x;
    if (idx >= MM) return;
    int i = idx >> 8;
    int j = idx & 255;
    unsigned int pos = (i == j) ? (unsigned int)(NN * (NN - 1) + i)
                                : (unsigned int)(i * (NN - 1) + (j < i ? j : j - 1));
    unsigned int key = atomic_key(x, idx);
    atomicMin(&g_aminpos[key], pos);
    atomicAdd(&g_acount[key], 1);
}

// One block, 1024 threads: rank = #(valid minpos < mine); write hist0 + arank.
__global__ void k_rankA(float* __restrict__ out0, int avail) {
    __shared__ unsigned int s[ATAB];
    int t = threadIdx.x;
    unsigned int v = g_aminpos[t];
    s[t] = v;
    __syncthreads();
    if (v != 0xFFFFFFFFu) {
        int rank = 0;
        #pragma unroll 8
        for (int u = 0; u < ATAB; u++) rank += (s[u] < v);
        g_arank[t] = rank;
        if (rank < avail) out0[rank] = (float)g_acount[t];
    }
}

__global__ void k_lblA(const int* __restrict__ x) {
    int idx = blockIdx.x * blockDim.x + threadIdx.x;
    if (idx >= MM) return;
    g_labels[idx] = g_arank[atomic_key(x, idx)];
}

// ---------------------------------------------------------------------------
// Multiset signatures: block b<256 -> rowsig[b], b>=256 -> colsig[b-256]
// ---------------------------------------------------------------------------
__global__ void k_sig() {
    __shared__ unsigned long long ws[8];
    int b = blockIdx.x, t = threadIdx.x;
    int lane = t & 31, w = t >> 5;
    int v = (b < NN) ? g_labels[(b << 8) + t]
                     : g_labels[(t << 8) + (b - NN)];
    unsigned long long h = sm64((unsigned long long)(unsigned int)v);
    #pragma unroll
    for (int off = 16; off > 0; off >>= 1)
        h += __shfl_down_sync(0xFFFFFFFFu, h, off);
    if (lane == 0) ws[w] = h;
    __syncthreads();
    if (t < 8) {
        unsigned long long hh = ws[t];
        #pragma unroll
        for (int off = 4; off > 0; off >>= 1)
            hh += __shfl_down_sync(0xFFu, hh, off);
        if (t == 0) {
            if (b < NN) g_rowsig[b] = hh;
            else        g_colsig[b - NN] = hh;
        }
    }
}

// ---------------------------------------------------------------------------
// Layer relabel (hash table, 64-bit keys)
// ---------------------------------------------------------------------------
__global__ void k_ins() {
    int idx = blockIdx.x * blockDim.x + threadIdx.x;
    if (idx >= MM) return;
    int i = idx >> 8;
    int j = idx & 255;
    unsigned long long key =
        sm64(g_rowsig[i] * 0xC2B2AE3D27D4EB4FULL
           ^ g_colsig[j] * 0x165667B19E3779F9ULL
           ^ ((unsigned long long)(unsigned int)g_labels[idx] + 1ULL)
               * 0x9E3779B97F4A7C15ULL);
    unsigned long long stored = key | 1ULL;
    unsigned int h = hash32((unsigned int)key ^ (unsigned int)(key >> 32)) & TABMASK;
    for (;;) {
        unsigned long long old = atomicCAS(&g_tab[h], 0ULL, stored);
        if (old == 0ULL || old == stored) break;
        h = (h + 1) & TABMASK;
    }
    atomicMin(&g_minpos[h], (unsigned int)idx);
    atomicAdd(&g_count[h], 1);
    g_slotid[idx] = (int)h;
}

__global__ void k_mark() {
    int t = blockIdx.x * blockDim.x + threadIdx.x;
    if (t < TAB && g_tab[t] != 0ULL) {
        unsigned int p = g_minpos[t];
        if (p < (unsigned int)MM) g_mark[p] = 1;
    }
}

// Single-pass scan: per-block scan + last-block scans the 64 block sums.
// Also clears g_mark for the next use.
__global__ void k_scan() {
    __shared__ int warp_sums[8];
    __shared__ int warp_excl[8];
    __shared__ int is_last;
    int b = blockIdx.x, t = threadIdx.x;
    int lane = t & 31, w = t >> 5;
    int4 v = g_mark4[b * 256 + t];
    g_mark4[b * 256 + t] = make_int4(0, 0, 0, 0);
    int s01 = v.x + v.y;
    int s012 = s01 + v.z;
    int tot = s012 + v.w;
    int inc = tot;
    #pragma unroll
    for (int off = 1; off < 32; off <<= 1) {
        int n = __shfl_up_sync(0xFFFFFFFFu, inc, off);
        if (lane >= off) inc += n;
    }
    if (lane == 31) warp_sums[w] = inc;
    __syncthreads();
    if (t < 8) {
        int ws = warp_sums[t];
        int inc2 = ws;
        #pragma unroll
        for (int off = 1; off < 8; off <<= 1) {
            int n = __shfl_up_sync(0xFFu, inc2, off);
            if (t >= off) inc2 += n;
        }
        warp_excl[t] = inc2 - ws;
    }
    __syncthreads();
    int base = warp_excl[w] + inc - tot;
    int4 e;
    e.x = base;
    e.y = base + v.x;
    e.z = base + s01;
    e.w = base + s012;
    g_rank4[b * 256 + t] = e;
    if (t == 255) g_bsum[b] = warp_excl[7] + inc;
    // last-arriving block scans the block sums
    __threadfence();
    __syncthreads();
    if (t == 0) {
        unsigned int done = atomicAdd(&g_scancnt, 1u);
        is_last = (done == 63u);
    }
    __syncthreads();
    if (is_last) {
        __threadfence();
        __shared__ int sh[64];
        if (t < 64) {
            int bv = g_bsum[t];
            sh[t] = bv;
            __syncthreads();
            #pragma unroll
            for (int off = 1; off < 64; off <<= 1) {
                int tmp = (t >= off) ? sh[t - off] : 0;
                __syncthreads();
                sh[t] += tmp;
                __syncthreads();
            }
            g_boff[t] = sh[t] - bv;
            if (t == 0) g_scancnt = 0u;
        } else {
            // keep all threads participating in the barriers above
            __syncthreads();
            #pragma unroll
            for (int off = 1; off < 64; off <<= 1) {
                __syncthreads();
                __syncthreads();
            }
        }
    }
}

// Write histogram (float) + per-slot rank; clean slots for next layer/replay.
__global__ void k_finish(float* __restrict__ dst, int avail) {
    int t = blockIdx.x * blockDim.x + threadIdx.x;
    if (t >= TAB) return;
    if (g_tab[t] != 0ULL) {
        unsigned int p = g_minpos[t] & (MM - 1);
        int r = (g_rank[p] + g_boff[p >> 10]) & (MM - 1);
        g_slotrank[t] = r;
        if (r < avail) dst[r] = (float)g_count[t];
        g_tab[t] = 0ULL;
        g_minpos[t] = 0xFFFFFFFFu;
        g_count[t] = 0;
    }
}

__global__ void k_lbl() {
    int idx = blockIdx.x * blockDim.x + threadIdx.x;
    if (idx >= MM) return;
    g_labels[idx] = g_slotrank[(unsigned int)g_slotid[idx] & TABMASK];
}

// ---------------------------------------------------------------------------
extern "C" void kernel_launch(void* const* d_in, const int* in_sizes, int n_in,
                              void* d_out, int out_size) {
    int xi = 0, ei_i = 1;
    if (n_in >= 2 && in_sizes[0] > in_sizes[1]) { xi = 1; ei_i = 0; }
    const int* x  = (const int*)d_in[xi];
    const int* ei = (const int*)d_in[ei_i];
    int E = in_sizes[ei_i] / 2;
    if (E == 4 * 8192) E = 8192;
    float* out = (float*)d_out;

    k_init<<<512, 256>>>(out, out_size);
    k_edges<<<(E + 255) / 256, 256>>>(ei, E);

    // --- atomic coloring ---
    k_insA<<<256, 256>>>(x);
    {
        int avail = out_size < MM ? out_size : MM;
        k_rankA<<<1, 1024>>>(out, avail);
    }
    k_lblA<<<256, 256>>>(x);

    // --- 2 refinement layers ---
    for (int l = 0; l < 2; l++) {
        k_sig<<<512, 256>>>();
        k_ins<<<256, 256>>>();
        k_mark<<<512, 256>>>();
        k_scan<<<64, 256>>>();
        int off = (l + 1) * MM;
        int avail = out_size - off;
        if (avail > MM) avail = MM;
        if (avail < 0) avail = 0;
        k_finish<<<512, 256>>>(out + off, avail);
        if (l == 0) k_lbl<<<256, 256>>>();
    }
}

// round 8
// speedup vs baseline: 5.0255x; 1.1466x over previous
#include <cuda_runtime.h>
#include <stdint.h>

// ---------------------------------------------------------------------------
// TwoWL: 2-layer 2-WL coloring, N=256, M=65536. Output: 3 float32 histograms.
// Multiset-hash formulation (commutative 64-bit hash sum per row/col).
// ---------------------------------------------------------------------------

#define NN 256
#define MM 65536
#define TAB 131072
#define TABMASK (TAB - 1)
#define ATAB 1024
#define ATABMASK (ATAB - 1)

__device__ unsigned int       g_Abits[MM / 32];   // adjacency bitset
__device__ int                g_labels[MM];
__device__ unsigned long long g_rowsig[NN];
__device__ unsigned long long g_colsig[NN];
__device__ unsigned long long g_tab[TAB];
__device__ unsigned int       g_minpos[TAB];
__device__ int                g_count[TAB];
__device__ int                g_slotrank[TAB];
__device__ int                g_slotid[MM];
__device__ unsigned int       g_aminpos[ATAB];
__device__ int                g_acount[ATAB];
__device__ int                g_arank[ATAB];
__device__ int4               g_mark4[MM / 4];
__device__ int4               g_rank4[MM / 4];
__device__ int                g_bsum[64];
__device__ int                g_boff[64];
__device__ unsigned int       g_scancnt;          // self-resetting (k_scan)

#define g_mark ((int*)g_mark4)
#define g_rank ((int*)g_rank4)

__device__ __forceinline__ unsigned long long sm64(unsigned long long z) {
    z += 0x9E3779B97F4A7C15ULL;
    z = (z ^ (z >> 30)) * 0xBF58476D1CE4E5B9ULL;
    z = (z ^ (z >> 27)) * 0x94D049BB133111EBULL;
    return z ^ (z >> 31);
}

__device__ __forceinline__ unsigned int hash32(unsigned int x) {
    x ^= x >> 16; x *= 0x7feb352du;
    x ^= x >> 15; x *= 0x846ca68bu;
    x ^= x >> 16;
    return x;
}

__device__ __forceinline__ unsigned int abit(int idx) {
    return (g_Abits[idx >> 5] >> (idx & 31)) & 1u;
}

__device__ __forceinline__ unsigned int atomic_key(const int* __restrict__ x, int idx) {
    int i = idx >> 8;
    int j = idx & 255;
    unsigned int key = ((unsigned int)x[i] << 5) | ((unsigned int)x[j] << 1) | abit(idx);
    return key & ATABMASK;
}

// ---------------------------------------------------------------------------
// Init: establish ALL invariants every launch (globals are only guaranteed
// zero-initialized at module load; self-cleaning keeps them clean only
// between the two layers within one launch).
// ---------------------------------------------------------------------------
__global__ void k_init(float* out, int out_size) {
    int gid = blockIdx.x * blockDim.x + threadIdx.x;
    int stride = gridDim.x * blockDim.x;
    for (int i = gid; i < out_size; i += stride) out[i] = 0.0f;
    for (int i = gid; i < MM / 32; i += stride) g_Abits[i] = 0u;
    for (int i = gid; i < TAB; i += stride) {
        g_tab[i] = 0ULL;
        g_minpos[i] = 0xFFFFFFFFu;
        g_count[i] = 0;
    }
    for (int i = gid; i < MM; i += stride) g_mark[i] = 0;
    if (gid < ATAB) { g_aminpos[gid] = 0xFFFFFFFFu; g_acount[gid] = 0; }
    if (gid == 0) g_scancnt = 0u;
}

__global__ void k_edges(const int* __restrict__ ei, int E) {
    int e = blockIdx.x * blockDim.x + threadIdx.x;
    if (e < E) {
        unsigned int s = (unsigned int)ei[e] & 255u;
        unsigned int d = (unsigned int)ei[E + e] & 255u;
        unsigned int idx = s * NN + d;
        atomicOr(&g_Abits[idx >> 5], 1u << (idx & 31));
    }
}

// ---------------------------------------------------------------------------
// Atomic layer
// ---------------------------------------------------------------------------
__global__ void k_insA(const int* __restrict__ x) {
    int idx = blockIdx.x * blockDim.x + threadIdx.x;
    if (idx >= MM) return;
    int i = idx >> 8;
    int j = idx & 255;
    unsigned int pos = (i == j) ? (unsigned int)(NN * (NN - 1) + i)
                                : (unsigned int)(i * (NN - 1) + (j < i ? j : j - 1));
    unsigned int key = atomic_key(x, idx);
    atomicMin(&g_aminpos[key], pos);
    atomicAdd(&g_acount[key], 1);
}

// 64 blocks x 256 threads: slot ranked by a 16-lane subgroup over the 1024
// shared values. Writes hist0 directly.
__global__ void k_rankA(float* __restrict__ out0, int avail) {
    __shared__ unsigned int s[ATAB];
    int t = threadIdx.x;
    #pragma unroll
    for (int u = 0; u < 4; u++) s[t + 256 * u] = g_aminpos[t + 256 * u];
    __syncthreads();
    int slot = blockIdx.x * 16 + (t >> 4);
    int lane16 = t & 15;
    unsigned int v = s[slot];
    int partial = 0;
    #pragma unroll 4
    for (int u = lane16; u < ATAB; u += 16) partial += (s[u] < v);
    #pragma unroll
    for (int off = 8; off > 0; off >>= 1)
        partial += __shfl_down_sync(0xFFFFFFFFu, partial, off, 16);
    if (lane16 == 0 && v != 0xFFFFFFFFu) {
        g_arank[slot] = partial;
        if (partial < avail) out0[partial] = (float)g_acount[slot];
    }
}

// ---------------------------------------------------------------------------
// Multiset signatures. Block b<256 -> rowsig[b] (also writes g_labels for the
// row); b>=256 -> colsig[b-256]. Labels recomputed inline per mode:
//   mode 0: arank[atomic_key]   mode 1: slotrank[slotid]
// ---------------------------------------------------------------------------
__global__ void k_sig(int mode, const int* __restrict__ x) {
    __shared__ unsigned long long ws[8];
    int b = blockIdx.x, t = threadIdx.x;
    int lane = t & 31, w = t >> 5;
    bool isRow = (b < NN);
    int idx = isRow ? ((b << 8) + t) : ((t << 8) + (b - NN));
    int lab;
    if (mode == 0) lab = g_arank[atomic_key(x, idx)];
    else           lab = g_slotrank[(unsigned int)g_slotid[idx] & TABMASK];
    if (isRow) g_labels[idx] = lab;
    unsigned long long h = sm64((unsigned long long)(unsigned int)lab);
    #pragma unroll
    for (int off = 16; off > 0; off >>= 1)
        h += __shfl_down_sync(0xFFFFFFFFu, h, off);
    if (lane == 0) ws[w] = h;
    __syncthreads();
    if (t < 8) {
        unsigned long long hh = ws[t];
        #pragma unroll
        for (int off = 4; off > 0; off >>= 1)
            hh += __shfl_down_sync(0xFFu, hh, off);
        if (t == 0) {
            if (isRow) g_rowsig[b] = hh;
            else       g_colsig[b - NN] = hh;
        }
    }
}

// ---------------------------------------------------------------------------
// Layer relabel (hash table, 64-bit keys)
// ---------------------------------------------------------------------------
__global__ void k_ins() {
    int idx = blockIdx.x * blockDim.x + threadIdx.x;
    if (idx >= MM) return;
    int i = idx >> 8;
    int j = idx & 255;
    unsigned long long key =
        sm64(g_rowsig[i] * 0xC2B2AE3D27D4EB4FULL
           ^ g_colsig[j] * 0x165667B19E3779F9ULL
           ^ ((unsigned long long)(unsigned int)g_labels[idx] + 1ULL)
               * 0x9E3779B97F4A7C15ULL);
    unsigned long long stored = key | 1ULL;
    unsigned int h = hash32((unsigned int)key ^ (unsigned int)(key >> 32)) & TABMASK;
    for (;;) {
        unsigned long long old = atomicCAS(&g_tab[h], 0ULL, stored);
        if (old == 0ULL || old == stored) break;
        h = (h + 1) & TABMASK;
    }
    atomicMin(&g_minpos[h], (unsigned int)idx);
    atomicAdd(&g_count[h], 1);
    g_slotid[idx] = (int)h;
}

__global__ void k_mark() {
    int t = blockIdx.x * blockDim.x + threadIdx.x;
    if (t < TAB && g_tab[t] != 0ULL) {
        unsigned int p = g_minpos[t];
        if (p < (unsigned int)MM) g_mark[p] = 1;
    }
}

// Single-pass scan over g_mark (64 blocks x 256 thr, int4). Clears g_mark
// (needed between layers). Last block scans the 64 block sums with one warp.
__global__ void k_scan() {
    __shared__ int warp_sums[8];
    __shared__ int warp_excl[8];
    __shared__ int is_last;
    int b = blockIdx.x, t = threadIdx.x;
    int lane = t & 31, w = t >> 5;
    int4 v = g_mark4[b * 256 + t];
    g_mark4[b * 256 + t] = make_int4(0, 0, 0, 0);
    int s01 = v.x + v.y;
    int s012 = s01 + v.z;
    int tot = s012 + v.w;
    int inc = tot;
    #pragma unroll
    for (int off = 1; off < 32; off <<= 1) {
        int n = __shfl_up_sync(0xFFFFFFFFu, inc, off);
        if (lane >= off) inc += n;
    }
    if (lane == 31) warp_sums[w] = inc;
    __syncthreads();
    if (t < 8) {
        int ws = warp_sums[t];
        int inc2 = ws;
        #pragma unroll
        for (int off = 1; off < 8; off <<= 1) {
            int n = __shfl_up_sync(0xFFu, inc2, off);
            if (t >= off) inc2 += n;
        }
        warp_excl[t] = inc2 - ws;
    }
    __syncthreads();
    int base = warp_excl[w] + inc - tot;
    int4 e;
    e.x = base;
    e.y = base + v.x;
    e.z = base + s01;
    e.w = base + s012;
    g_rank4[b * 256 + t] = e;
    if (t == 255) g_bsum[b] = warp_excl[7] + inc;
    __threadfence();
    __syncthreads();
    if (t == 0) {
        unsigned int done = atomicAdd(&g_scancnt, 1u);
        is_last = (done == 63u);
    }
    __syncthreads();
    if (is_last && t < 32) {
        __threadfence();
        int v0 = g_bsum[2 * t];
        int v1 = g_bsum[2 * t + 1];
        int p = v0 + v1;
        int inc3 = p;
        #pragma unroll
        for (int off = 1; off < 32; off <<= 1) {
            int n = __shfl_up_sync(0xFFFFFFFFu, inc3, off);
            if (t >= off) inc3 += n;
        }
        int excl = inc3 - p;
        g_boff[2 * t] = excl;
        g_boff[2 * t + 1] = excl + v0;
        if (t == 0) g_scancnt = 0u;
    }
}

// Write histogram (float) + per-slot rank; self-clean slots (needed so layer 2
// starts from a clean table within the same launch).
__global__ void k_finish(float* __restrict__ dst, int avail) {
    int t = blockIdx.x * blockDim.x + threadIdx.x;
    if (t >= TAB) return;
    if (g_tab[t] != 0ULL) {
        unsigned int p = g_minpos[t] & (MM - 1);
        int r = (g_rank[p] + g_boff[p >> 10]) & (MM - 1);
        g_slotrank[t] = r;
        if (r < avail) dst[r] = (float)g_count[t];
        g_tab[t] = 0ULL;
        g_minpos[t] = 0xFFFFFFFFu;
        g_count[t] = 0;
    }
}

// ---------------------------------------------------------------------------
extern "C" void kernel_launch(void* const* d_in, const int* in_sizes, int n_in,
                              void* d_out, int out_size) {
    int xi = 0, ei_i = 1;
    if (n_in >= 2 && in_sizes[0] > in_sizes[1]) { xi = 1; ei_i = 0; }
    const int* x  = (const int*)d_in[xi];
    const int* ei = (const int*)d_in[ei_i];
    int E = in_sizes[ei_i] / 2;
    if (E == 4 * 8192) E = 8192;
    float* out = (float*)d_out;

    k_init<<<256, 256>>>(out, out_size);
    k_edges<<<(E + 255) / 256, 256>>>(ei, E);

    // --- atomic coloring ---
    k_insA<<<256, 256>>>(x);
    {
        int avail = out_size < MM ? out_size : MM;
        k_rankA<<<64, 256>>>(out, avail);
    }

    // --- 2 refinement layers (labels recomputed inline in k_sig) ---
    for (int l = 0; l < 2; l++) {
        k_sig<<<512, 256>>>(l == 0 ? 0 : 1, x);
        k_ins<<<256, 256>>>();
        k_mark<<<512, 256>>>();
        k_scan<<<64, 256>>>();
        int off = (l + 1) * MM;
        int avail = out_size - off;
        if (avail > MM) avail = MM;
        if (avail < 0) avail = 0;
        k_finish<<<512, 256>>>(out + off, avail);
    }
}